// round 1
// baseline (speedup 1.0000x reference)
#include <cuda_runtime.h>

// Problem constants (fixed shapes)
#define VF    128            // V*F = 8*16
#define CCH   1024
#define HH    14
#define WW    14
#define NBOX  768
#define GG    8              // grid = OUT_SIZE+1
#define OUTS  7
#define CHT   64             // channels per block tile
#define PSTR  197            // padded plane stride (odd -> conflict-free banks)
#define SCALE (1.0f/16.0f)

#define ROI_COUNT   ((size_t)NBOX * CCH * OUTS * OUTS)   // 38,535,168
#define SNODE_OFF   (ROI_COUNT)
#define SNODE_COUNT ((size_t)VF * CCH)                   // 131,072
#define FAKE_OFF    (SNODE_OFF + SNODE_COUNT)            // 38,666,240

// ---------------------------------------------------------------------------
// Kernel 1: RoIAlignAvg
// block = (box n, 64-channel tile). Loads the needed rows of 64 channel planes
// into SMEM (coalesced), computes the 8x8 bilinear grid row-streaming per
// channel, 2x2 avg-pools to 7x7 into an SMEM staging buffer, then writes the
// contiguous 64*49-float output chunk coalesced.
// ---------------------------------------------------------------------------
__global__ __launch_bounds__(256) void roi_kernel(
    const float* __restrict__ feat,
    const float* __restrict__ boxes,
    const int*   __restrict__ fidx,
    float*       __restrict__ out)
{
    extern __shared__ float sm[];
    float* plane = sm;                     // CHT * PSTR floats
    float* outsm = sm + CHT * PSTR;        // CHT * 49 floats

    __shared__ int   s_x0[GG], s_x1[GG], s_y0[GG], s_y1[GG];
    __shared__ float s_wx[GG], s_wy[GG];

    const int tid = threadIdx.x;
    const int n   = blockIdx.x >> 4;       // 1024/64 = 16 tiles per box
    const int c0  = (blockIdx.x & 15) * CHT;

    if (tid < GG) {
        float t   = (float)tid / 7.0f;
        float bx1 = boxes[n*4+0]*SCALE, by1 = boxes[n*4+1]*SCALE;
        float bx2 = boxes[n*4+2]*SCALE, by2 = boxes[n*4+3]*SCALE;
        float xs  = fminf(fmaxf(bx1 + t*(bx2-bx1), 0.0f), (float)(WW-1));
        float ys  = fminf(fmaxf(by1 + t*(by2-by1), 0.0f), (float)(HH-1));
        int x0 = (int)floorf(xs);
        int y0 = (int)floorf(ys);
        s_x0[tid] = x0; s_x1[tid] = min(x0+1, WW-1); s_wx[tid] = xs - (float)x0;
        s_y0[tid] = y0; s_y1[tid] = min(y0+1, HH-1); s_wy[tid] = ys - (float)y0;
    }
    __syncthreads();

    // boxes have x2>=x1, y2>=y1 -> ys monotone nondecreasing over grid index
    const int ry0  = s_y0[0];
    const int rows = s_y1[GG-1] - ry0 + 1;
    const int L    = rows * WW;
    const int b    = fidx[n];
    const float* fbase = feat + ((size_t)b * CCH + c0) * (HH*WW) + ry0 * WW;

    // ---- load phase: coalesced, only the needed rows per channel ----
    const int warp = tid >> 5, lane = tid & 31;
    for (int c = warp; c < CHT; c += 8) {
        const float* src = fbase + c * (HH*WW);
        float*       dst = plane + c * PSTR;
        for (int r = lane; r < L; r += 32) dst[r] = src[r];
    }
    __syncthreads();

    // ---- compute phase: lane = channel (stride 197 -> conflict-free) ----
    const int c  = tid & (CHT-1);
    const int q  = tid >> 6;                 // 0..3: split pooled rows
    const int py_lo = q * 2;
    const int py_hi = min(py_lo + 1, OUTS-1);
    const float* pl = plane + c * PSTR;

    float gcur[GG], gprev[GG];
    for (int gy = py_lo; gy <= py_hi + 1; ++gy) {
        const float wyv = s_wy[gy];
        const int ra = (s_y0[gy] - ry0) * WW;
        const int rb = (s_y1[gy] - ry0) * WW;
        #pragma unroll
        for (int gx = 0; gx < GG; ++gx) {
            const float wxv = s_wx[gx];
            const int xa = s_x0[gx], xb = s_x1[gx];
            const float a0 = pl[ra + xa], a1 = pl[ra + xb];
            const float b0 = pl[rb + xa], b1 = pl[rb + xb];
            const float top = a0 + wxv * (a1 - a0);
            const float bot = b0 + wxv * (b1 - b0);
            gcur[gx] = top + wyv * (bot - top);
        }
        if (gy > py_lo) {
            const int py = gy - 1;
            float* od = outsm + c * (OUTS*OUTS) + py * OUTS;
            #pragma unroll
            for (int px = 0; px < OUTS; ++px)
                od[px] = 0.25f * (gprev[px] + gprev[px+1] + gcur[px] + gcur[px+1]);
        }
        #pragma unroll
        for (int gx = 0; gx < GG; ++gx) gprev[gx] = gcur[gx];
    }
    __syncthreads();

    // ---- store phase: contiguous coalesced copy ----
    float* op = out + ((size_t)n * CCH + c0) * (OUTS*OUTS);
    for (int i = tid; i < CHT * OUTS * OUTS; i += 256) op[i] = outsm[i];
}

// ---------------------------------------------------------------------------
// Kernel 2: fused s_node (mean over HxW) + fake_h_s (slice [1:13,1:13]).
// One warp per (b,c) plane: single coalesced read of 196 floats, warp-reduce
// mean, slice written inline.
// ---------------------------------------------------------------------------
__global__ __launch_bounds__(256) void snode_fake_kernel(
    const float* __restrict__ feat,
    float*       __restrict__ out)
{
    const int warp = threadIdx.x >> 5;
    const int lane = threadIdx.x & 31;
    const size_t planeidx = (size_t)blockIdx.x * 8 + warp;
    if (planeidx >= (size_t)VF * CCH) return;

    const float* src  = feat + planeidx * (HH*WW);
    float*       fake = out + FAKE_OFF + planeidx * 144;

    float sum = 0.0f;
    #pragma unroll
    for (int k = 0; k < 7; ++k) {
        const int r = lane + k * 32;
        if (r < HH*WW) {
            const float v = src[r];
            sum += v;
            const int y = r / WW;
            const int x = r - y * WW;
            if (y >= 1 && y <= 12 && x >= 1 && x <= 12)
                fake[(y-1)*12 + (x-1)] = v;
        }
    }
    #pragma unroll
    for (int o = 16; o; o >>= 1)
        sum += __shfl_down_sync(0xFFFFFFFFu, sum, o);
    if (lane == 0)
        out[SNODE_OFF + planeidx] = sum * (1.0f / 196.0f);
}

// ---------------------------------------------------------------------------
extern "C" void kernel_launch(void* const* d_in, const int* in_sizes, int n_in,
                              void* d_out, int out_size)
{
    const float* feat  = (const float*)d_in[0];
    const float* boxes = (const float*)d_in[1];
    const int*   fidx  = (const int*)d_in[2];
    float*       out   = (float*)d_out;

    const int roi_smem = (CHT * PSTR + CHT * OUTS * OUTS) * (int)sizeof(float); // 62,976 B
    cudaFuncSetAttribute(roi_kernel,
                         cudaFuncAttributeMaxDynamicSharedMemorySize, roi_smem);

    roi_kernel<<<NBOX * (CCH / CHT), 256, roi_smem>>>(feat, boxes, fidx, out);

    const int nplanes = VF * CCH;                 // 131072
    snode_fake_kernel<<<nplanes / 8, 256>>>(feat, out);
}

// round 3
// speedup vs baseline: 1.3019x; 1.3019x over previous
#include <cuda_runtime.h>
#include <cstdint>

// Problem constants (fixed shapes)
#define VF    128            // V*F = 8*16
#define CCH   1024
#define HH    14
#define WW    14
#define NBOX  768
#define GG    8              // grid = OUT_SIZE+1
#define OUTS  7
#define CHT   64             // channels per block tile
#define PSTR  197            // padded plane stride (odd -> conflict-free banks)
#define SCALE (1.0f/16.0f)

#define ROI_BLOCKS   (NBOX * (CCH / CHT))                 // 12288
#define SNODE_BLOCKS ((VF * CCH) / 8)                     // 16384

#define ROI_COUNT   ((size_t)NBOX * CCH * OUTS * OUTS)   // 38,535,168
#define SNODE_OFF   (ROI_COUNT)
#define FAKE_OFF    (SNODE_OFF + (size_t)VF * CCH)       // 38,666,240

__device__ __forceinline__ void cp_async4(unsigned int smem_dst, const void* gmem_src) {
    asm volatile("cp.async.ca.shared.global [%0], [%1], 4;\n"
                 :: "r"(smem_dst), "l"(gmem_src) : "memory");
}

// ---------------------------------------------------------------------------
// Fused kernel. Blocks [0, ROI_BLOCKS) do RoIAlignAvg; the rest do the
// s_node mean + fake_h_s slice. One launch lets the short snode work overlap
// the long roi work instead of serializing behind it.
// ---------------------------------------------------------------------------
__global__ __launch_bounds__(256) void fused_kernel(
    const float* __restrict__ feat,
    const float* __restrict__ boxes,
    const int*   __restrict__ fidx,
    float*       __restrict__ out)
{
    extern __shared__ float sm[];

    if (blockIdx.x >= ROI_BLOCKS) {
        // ---------------- snode + fake_h_s branch -------------------------
        const int warp = threadIdx.x >> 5;
        const int lane = threadIdx.x & 31;
        const size_t planeidx = (size_t)(blockIdx.x - ROI_BLOCKS) * 8 + warp;

        const float* src  = feat + planeidx * (HH*WW);
        float*       fake = out + FAKE_OFF + planeidx * 144;

        float sum = 0.0f;
        #pragma unroll
        for (int k = 0; k < 7; ++k) {
            const int r = lane + k * 32;
            if (r < HH*WW) {
                const float v = src[r];
                sum += v;
                const int y = r / WW;
                const int x = r - y * WW;
                if (y >= 1 && y <= 12 && x >= 1 && x <= 12)
                    fake[(y-1)*12 + (x-1)] = v;
            }
        }
        #pragma unroll
        for (int o = 16; o; o >>= 1)
            sum += __shfl_down_sync(0xFFFFFFFFu, sum, o);
        if (lane == 0)
            out[SNODE_OFF + planeidx] = sum * (1.0f / 196.0f);
        return;
    }

    // -------------------------- RoI branch --------------------------------
    float* plane = sm;                     // CHT * PSTR floats
    float* outsm = sm + CHT * PSTR;        // CHT * 49 floats

    __shared__ int   s_x0[GG], s_x1[GG], s_y0[GG], s_y1[GG];
    __shared__ float s_wx[GG], s_wy[GG];

    const int tid = threadIdx.x;
    const int n   = blockIdx.x >> 4;       // 1024/64 = 16 tiles per box
    const int c0  = (blockIdx.x & 15) * CHT;

    if (tid < GG) {
        float t   = (float)tid / 7.0f;
        float bx1 = boxes[n*4+0]*SCALE, by1 = boxes[n*4+1]*SCALE;
        float bx2 = boxes[n*4+2]*SCALE, by2 = boxes[n*4+3]*SCALE;
        float xs  = fminf(fmaxf(bx1 + t*(bx2-bx1), 0.0f), (float)(WW-1));
        float ys  = fminf(fmaxf(by1 + t*(by2-by1), 0.0f), (float)(HH-1));
        int x0 = (int)floorf(xs);
        int y0 = (int)floorf(ys);
        s_x0[tid] = x0; s_x1[tid] = min(x0+1, WW-1); s_wx[tid] = xs - (float)x0;
        s_y0[tid] = y0; s_y1[tid] = min(y0+1, HH-1); s_wy[tid] = ys - (float)y0;
    }
    __syncthreads();

    // boxes have x2>=x1, y2>=y1 -> ys monotone nondecreasing over grid index
    const int ry0  = s_y0[0];
    const int rows = s_y1[GG-1] - ry0 + 1;
    const int L    = rows * WW;            // contiguous span per channel
    const int b    = fidx[n];
    const float* fbase = feat + ((size_t)b * CCH + c0) * (HH*WW) + ry0 * WW;

    // ---- load phase: cp.async, fully unrolled -> high MLP, no reg deps ----
    const int warp = tid >> 5, lane = tid & 31;
    {
        const unsigned int smem_base = (unsigned int)__cvta_generic_to_shared(plane);
        #pragma unroll
        for (int j = 0; j < 8; ++j) {
            const int c = warp + j * 8;
            const float*      src = fbase + c * (HH*WW);
            const unsigned int dst = smem_base + (unsigned int)(c * PSTR) * 4u;
            #pragma unroll
            for (int k = 0; k < 7; ++k) {
                const int r = lane + k * 32;
                if (r < L) cp_async4(dst + (unsigned int)r * 4u, src + r);
            }
        }
        asm volatile("cp.async.commit_group;\n" ::: "memory");
        asm volatile("cp.async.wait_group 0;\n" ::: "memory");
    }
    __syncthreads();

    // ---- compute phase: lane = channel (stride 197 -> conflict-free) ----
    const int c  = tid & (CHT-1);
    const int q  = tid >> 6;                 // 0..3: split pooled rows
    const int py_lo = q * 2;
    const int py_hi = min(py_lo + 1, OUTS-1);
    const float* pl = plane + c * PSTR;

    float gcur[GG], gprev[GG];
    for (int gy = py_lo; gy <= py_hi + 1; ++gy) {
        const float wyv = s_wy[gy];
        const int ra = (s_y0[gy] - ry0) * WW;
        const int rb = (s_y1[gy] - ry0) * WW;
        #pragma unroll
        for (int gx = 0; gx < GG; ++gx) {
            const float wxv = s_wx[gx];
            const int xa = s_x0[gx], xb = s_x1[gx];
            const float a0 = pl[ra + xa], a1 = pl[ra + xb];
            const float b0 = pl[rb + xa], b1 = pl[rb + xb];
            const float top = a0 + wxv * (a1 - a0);
            const float bot = b0 + wxv * (b1 - b0);
            gcur[gx] = top + wyv * (bot - top);
        }
        if (gy > py_lo) {
            const int py = gy - 1;
            float* od = outsm + c * (OUTS*OUTS) + py * OUTS;
            #pragma unroll
            for (int px = 0; px < OUTS; ++px)
                od[px] = 0.25f * (gprev[px] + gprev[px+1] + gcur[px] + gcur[px+1]);
        }
        #pragma unroll
        for (int gx = 0; gx < GG; ++gx) gprev[gx] = gcur[gx];
    }
    __syncthreads();

    // ---- store phase: vectorized contiguous coalesced copy ----
    // (n*CCH + c0) is a multiple of 64 -> byte offset multiple of 12544 -> 16B OK
    {
        const float4* src4 = (const float4*)outsm;
        float4*       dst4 = (float4*)(out + ((size_t)n * CCH + c0) * (OUTS*OUTS));
        #pragma unroll
        for (int i = tid; i < (CHT * OUTS * OUTS) / 4; i += 256)
            dst4[i] = src4[i];
    }
}

// ---------------------------------------------------------------------------
extern "C" void kernel_launch(void* const* d_in, const int* in_sizes, int n_in,
                              void* d_out, int out_size)
{
    const float* feat  = (const float*)d_in[0];
    const float* boxes = (const float*)d_in[1];
    const int*   fidx  = (const int*)d_in[2];
    float*       out   = (float*)d_out;

    const int roi_smem = (CHT * PSTR + CHT * OUTS * OUTS) * (int)sizeof(float); // 62,976 B
    cudaFuncSetAttribute(fused_kernel,
                         cudaFuncAttributeMaxDynamicSharedMemorySize, roi_smem);

    fused_kernel<<<ROI_BLOCKS + SNODE_BLOCKS, 256, roi_smem>>>(feat, boxes, fidx, out);
}

// round 4
// speedup vs baseline: 1.7298x; 1.3287x over previous
#include <cuda_runtime.h>
#include <cstdint>

// Problem constants (fixed shapes)
#define VF    128            // V*F = 8*16
#define CCH   1024
#define HH    14
#define WW    14
#define NBOX  768
#define GG    8              // grid = OUT_SIZE+1
#define OUTS  7
#define CHT   32             // channels per block tile (32 -> ~31.5KB smem, 7 blocks/SM)
#define TILES (CCH / CHT)    // 32
#define PSTR  197            // padded plane stride (197 % 32 = 5, coprime -> conflict-free)
#define SCALE (1.0f/16.0f)

#define ROI_BLOCKS   (NBOX * TILES)                      // 24576
#define SNODE_BLOCKS ((VF * CCH) / 8)                    // 16384

#define ROI_COUNT   ((size_t)NBOX * CCH * OUTS * OUTS)   // 38,535,168
#define SNODE_OFF   (ROI_COUNT)
#define FAKE_OFF    (SNODE_OFF + (size_t)VF * CCH)       // 38,666,240

__device__ __forceinline__ void cp_async4(unsigned int smem_dst, const void* gmem_src) {
    asm volatile("cp.async.ca.shared.global [%0], [%1], 4;\n"
                 :: "r"(smem_dst), "l"(gmem_src) : "memory");
}

// ---------------------------------------------------------------------------
// Fused kernel. Blocks [0, ROI_BLOCKS) do RoIAlignAvg; the rest do the
// s_node mean + fake_h_s slice.
// ---------------------------------------------------------------------------
__global__ __launch_bounds__(256) void fused_kernel(
    const float* __restrict__ feat,
    const float* __restrict__ boxes,
    const int*   __restrict__ fidx,
    float*       __restrict__ out)
{
    extern __shared__ float sm[];

    if (blockIdx.x >= ROI_BLOCKS) {
        // ---------------- snode + fake_h_s branch -------------------------
        const int warp = threadIdx.x >> 5;
        const int lane = threadIdx.x & 31;
        const size_t planeidx = (size_t)(blockIdx.x - ROI_BLOCKS) * 8 + warp;

        const float* src  = feat + planeidx * (HH*WW);
        float*       fake = out + FAKE_OFF + planeidx * 144;

        float sum = 0.0f;
        #pragma unroll
        for (int k = 0; k < 7; ++k) {
            const int r = lane + k * 32;
            if (r < HH*WW) {
                const float v = src[r];
                sum += v;
                const int y = r / WW;
                const int x = r - y * WW;
                if (y >= 1 && y <= 12 && x >= 1 && x <= 12)
                    fake[(y-1)*12 + (x-1)] = v;
            }
        }
        #pragma unroll
        for (int o = 16; o; o >>= 1)
            sum += __shfl_down_sync(0xFFFFFFFFu, sum, o);
        if (lane == 0)
            out[SNODE_OFF + planeidx] = sum * (1.0f / 196.0f);
        return;
    }

    // -------------------------- RoI branch --------------------------------
    float* plane = sm;                     // CHT * PSTR floats
    float* outsm = sm + CHT * PSTR;        // CHT * 49 floats

    __shared__ int   s_x0[GG], s_x1[GG], s_y0[GG], s_y1[GG];
    __shared__ float s_wx[GG], s_wy[GG];

    const int tid = threadIdx.x;
    const int n   = blockIdx.x / TILES;
    const int c0  = (blockIdx.x % TILES) * CHT;

    if (tid < GG) {
        float t   = (float)tid / 7.0f;
        float bx1 = boxes[n*4+0]*SCALE, by1 = boxes[n*4+1]*SCALE;
        float bx2 = boxes[n*4+2]*SCALE, by2 = boxes[n*4+3]*SCALE;
        float xs  = fminf(fmaxf(bx1 + t*(bx2-bx1), 0.0f), (float)(WW-1));
        float ys  = fminf(fmaxf(by1 + t*(by2-by1), 0.0f), (float)(HH-1));
        int x0 = (int)floorf(xs);
        int y0 = (int)floorf(ys);
        s_x0[tid] = x0; s_x1[tid] = min(x0+1, WW-1); s_wx[tid] = xs - (float)x0;
        s_y0[tid] = y0; s_y1[tid] = min(y0+1, HH-1); s_wy[tid] = ys - (float)y0;
    }
    __syncthreads();

    // ys monotone nondecreasing over grid index (x2>=x1, y2>=y1)
    const int ry0  = s_y0[0];
    const int rows = s_y1[GG-1] - ry0 + 1;
    const int L    = rows * WW;            // contiguous span per channel
    const int b    = fidx[n];
    const float* fbase = feat + ((size_t)b * CCH + c0) * (HH*WW) + ry0 * WW;

    // ---- load phase: cp.async, fully unrolled -> high MLP, no reg deps ----
    const int warp = tid >> 5, lane = tid & 31;
    {
        const unsigned int smem_base = (unsigned int)__cvta_generic_to_shared(plane);
        #pragma unroll
        for (int j = 0; j < CHT / 8; ++j) {          // 4 channels per warp
            const int c = warp + j * 8;
            const float*      src = fbase + c * (HH*WW);
            const unsigned int dst = smem_base + (unsigned int)(c * PSTR) * 4u;
            #pragma unroll
            for (int k = 0; k < 7; ++k) {
                const int r = lane + k * 32;
                if (r < L) cp_async4(dst + (unsigned int)r * 4u, src + r);
            }
        }
        asm volatile("cp.async.commit_group;\n" ::: "memory");
        asm volatile("cp.async.wait_group 0;\n" ::: "memory");
    }
    __syncthreads();

    // ---- compute phase: lane = channel (conflict-free), warp = pooled row --
    if (warp < OUTS) {
        const int py = warp;               // pooled row 0..6
        const float* pl = plane + lane * PSTR;

        float g0[GG], g1[GG];
        {
            const float wyv = s_wy[py];
            const int ra = (s_y0[py] - ry0) * WW;
            const int rb = (s_y1[py] - ry0) * WW;
            #pragma unroll
            for (int gx = 0; gx < GG; ++gx) {
                const float wxv = s_wx[gx];
                const float a0 = pl[ra + s_x0[gx]], a1 = pl[ra + s_x1[gx]];
                const float b0 = pl[rb + s_x0[gx]], b1 = pl[rb + s_x1[gx]];
                const float top = a0 + wxv * (a1 - a0);
                const float bot = b0 + wxv * (b1 - b0);
                g0[gx] = top + wyv * (bot - top);
            }
        }
        {
            const float wyv = s_wy[py+1];
            const int ra = (s_y0[py+1] - ry0) * WW;
            const int rb = (s_y1[py+1] - ry0) * WW;
            #pragma unroll
            for (int gx = 0; gx < GG; ++gx) {
                const float wxv = s_wx[gx];
                const float a0 = pl[ra + s_x0[gx]], a1 = pl[ra + s_x1[gx]];
                const float b0 = pl[rb + s_x0[gx]], b1 = pl[rb + s_x1[gx]];
                const float top = a0 + wxv * (a1 - a0);
                const float bot = b0 + wxv * (b1 - b0);
                g1[gx] = top + wyv * (bot - top);
            }
        }
        float* od = outsm + lane * (OUTS*OUTS) + py * OUTS;
        #pragma unroll
        for (int px = 0; px < OUTS; ++px)
            od[px] = 0.25f * (g0[px] + g0[px+1] + g1[px] + g1[px+1]);
    }
    __syncthreads();

    // ---- store phase: vectorized contiguous coalesced copy ----
    // c0 multiple of 32 -> output byte offset multiple of 6272 -> 16B aligned
    {
        const float4* src4 = (const float4*)outsm;
        float4*       dst4 = (float4*)(out + ((size_t)n * CCH + c0) * (OUTS*OUTS));
        #pragma unroll
        for (int i = tid; i < (CHT * OUTS * OUTS) / 4; i += 256)
            dst4[i] = src4[i];
    }
}

// ---------------------------------------------------------------------------
extern "C" void kernel_launch(void* const* d_in, const int* in_sizes, int n_in,
                              void* d_out, int out_size)
{
    const float* feat  = (const float*)d_in[0];
    const float* boxes = (const float*)d_in[1];
    const int*   fidx  = (const int*)d_in[2];
    float*       out   = (float*)d_out;

    const int roi_smem = (CHT * PSTR + CHT * OUTS * OUTS) * (int)sizeof(float); // 31,488 B
    cudaFuncSetAttribute(fused_kernel,
                         cudaFuncAttributeMaxDynamicSharedMemorySize, roi_smem);

    fused_kernel<<<ROI_BLOCKS + SNODE_BLOCKS, 256, roi_smem>>>(feat, boxes, fidx, out);
}

// round 5
// speedup vs baseline: 2.0951x; 1.2112x over previous
#include <cuda_runtime.h>
#include <cstdint>

// Problem constants (fixed shapes)
#define VF    128            // V*F = 8*16
#define CCH   1024
#define HH    14
#define WW    14
#define NBOX  768
#define GG    8              // grid = OUT_SIZE+1
#define OUTS  7
#define CHT   32             // channels per block tile
#define TILES (CCH / CHT)    // 32
#define PSTR  133            // padded plane stride; box span <= 9 rows -> max idx 125
#define SCALE (1.0f/16.0f)

#define ROI_BLOCKS   (NBOX * TILES)                      // 24576
#define SNODE_BLOCKS ((VF * CCH) / 8)                    // 16384

#define ROI_COUNT   ((size_t)NBOX * CCH * OUTS * OUTS)   // 38,535,168
#define SNODE_OFF   (ROI_COUNT)
#define FAKE_OFF    (SNODE_OFF + (size_t)VF * CCH)       // 38,666,240

__device__ __forceinline__ void cp_async4(unsigned int smem_dst, const void* gmem_src) {
    asm volatile("cp.async.ca.shared.global [%0], [%1], 4;\n"
                 :: "r"(smem_dst), "l"(gmem_src) : "memory");
}

// ---------------------------------------------------------------------------
// Fused kernel. Blocks [0, ROI_BLOCKS) do RoIAlignAvg; the rest do the
// s_node mean + fake_h_s slice.
// ---------------------------------------------------------------------------
__global__ __launch_bounds__(256, 8) void fused_kernel(
    const float* __restrict__ feat,
    const float* __restrict__ boxes,
    const int*   __restrict__ fidx,
    float*       __restrict__ out)
{
    extern __shared__ float sm[];

    if (blockIdx.x >= ROI_BLOCKS) {
        // ---------------- snode + fake_h_s branch -------------------------
        const int warp = threadIdx.x >> 5;
        const int lane = threadIdx.x & 31;
        const size_t planeidx = (size_t)(blockIdx.x - ROI_BLOCKS) * 8 + warp;

        const float* src  = feat + planeidx * (HH*WW);
        float*       fake = out + FAKE_OFF + planeidx * 144;

        float sum = 0.0f;
        #pragma unroll
        for (int k = 0; k < 7; ++k) {
            const int r = lane + k * 32;
            if (r < HH*WW) {
                const float v = src[r];
                sum += v;
                const int y = r / WW;
                const int x = r - y * WW;
                if (y >= 1 && y <= 12 && x >= 1 && x <= 12)
                    fake[(y-1)*12 + (x-1)] = v;
            }
        }
        #pragma unroll
        for (int o = 16; o; o >>= 1)
            sum += __shfl_down_sync(0xFFFFFFFFu, sum, o);
        if (lane == 0)
            out[SNODE_OFF + planeidx] = sum * (1.0f / 196.0f);
        return;
    }

    // -------------------------- RoI branch --------------------------------
    float* plane = sm;                     // CHT * PSTR floats
    float* outsm = sm + CHT * PSTR;        // CHT * 49 floats

    __shared__ int   s_x0[GG], s_x1[GG], s_y0[GG], s_y1[GG];
    __shared__ float s_wx[GG], s_wy[GG];

    const int tid = threadIdx.x;
    const int n   = blockIdx.x / TILES;
    const int c0  = (blockIdx.x % TILES) * CHT;

    if (tid < GG) {
        float t   = (float)tid / 7.0f;
        float bx1 = boxes[n*4+0]*SCALE, by1 = boxes[n*4+1]*SCALE;
        float bx2 = boxes[n*4+2]*SCALE, by2 = boxes[n*4+3]*SCALE;
        float xs  = fminf(fmaxf(bx1 + t*(bx2-bx1), 0.0f), (float)(WW-1));
        float ys  = fminf(fmaxf(by1 + t*(by2-by1), 0.0f), (float)(HH-1));
        int x0 = (int)floorf(xs);
        int y0 = (int)floorf(ys);
        s_x0[tid] = x0; s_x1[tid] = min(x0+1, WW-1); s_wx[tid] = xs - (float)x0;
        s_y0[tid] = y0; s_y1[tid] = min(y0+1, HH-1); s_wy[tid] = ys - (float)y0;
    }
    __syncthreads();

    // ys monotone nondecreasing; span <= 9 rows (box h <= 7 feature px)
    const int ry0  = s_y0[0];
    const int rows = s_y1[GG-1] - ry0 + 1;
    const int L    = rows * WW;            // contiguous span per channel, <= 126
    const int b    = fidx[n];
    const float* fbase = feat + ((size_t)b * CCH + c0) * (HH*WW) + ry0 * WW;

    // ---- load phase: cp.async, fully unrolled -> high MLP, no reg deps ----
    const int warp = tid >> 5, lane = tid & 31;
    {
        const unsigned int smem_base = (unsigned int)__cvta_generic_to_shared(plane);
        #pragma unroll
        for (int j = 0; j < CHT / 8; ++j) {          // 4 channels per warp
            const int c = warp + j * 8;
            const float*      src = fbase + c * (HH*WW);
            const unsigned int dst = smem_base + (unsigned int)(c * PSTR) * 4u;
            #pragma unroll
            for (int k = 0; k < 4; ++k) {            // L <= 126 -> k*32+lane < 128
                const int r = lane + k * 32;
                if (r < L) cp_async4(dst + (unsigned int)r * 4u, src + r);
            }
        }
        asm volatile("cp.async.commit_group;\n" ::: "memory");
        asm volatile("cp.async.wait_group 0;\n" ::: "memory");
    }
    __syncthreads();

    // ---- compute phase: thread = (channel, gx). All 256 threads active. ----
    // lane = gx + 8*chsub ; ch = warp*4 + chsub. Stream gy with warp-uniform
    // row caching (rows are per-box -> identical across lanes).
    {
        const int gx    = lane & 7;
        const int chsub = lane >> 3;
        const int ch    = warp * 4 + chsub;
        const float* pl = plane + ch * PSTR;

        const int   xa = s_x0[gx], xb = s_x1[gx];
        const float wx = s_wx[gx];

        int   curA = -1, curB = -1;
        float a0 = 0.f, a1 = 0.f, b0 = 0.f, b1 = 0.f;
        float xs_prev = 0.f;

        #pragma unroll
        for (int gy = 0; gy < GG; ++gy) {
            const int rA = s_y0[gy] - ry0;
            const int rB = s_y1[gy] - ry0;
            if (rA != curA) {                 // warp-uniform branch
                if (rA == curB) { a0 = b0; a1 = b1; }
                else            { a0 = pl[rA*WW + xa]; a1 = pl[rA*WW + xb]; }
                curA = rA;
            }
            if (rB != curB) {                 // warp-uniform branch
                b0 = pl[rB*WW + xa]; b1 = pl[rB*WW + xb];
                curB = rB;
            }
            const float wy  = s_wy[gy];
            const float top = a0 + wx * (a1 - a0);
            const float bot = b0 + wx * (b1 - b0);
            const float g   = top + wy * (bot - top);
            // x-pool: neighbor gx+1 within the 8-lane group
            const float gr = __shfl_down_sync(0xFFFFFFFFu, g, 1, 8);
            const float xs = g + gr;
            if (gy > 0 && gx < OUTS)
                outsm[ch * (OUTS*OUTS) + (gy-1) * OUTS + gx] = 0.25f * (xs_prev + xs);
            xs_prev = xs;
        }
    }
    __syncthreads();

    // ---- store phase: vectorized contiguous coalesced copy ----
    // c0 multiple of 32 -> output byte offset multiple of 6272 -> 16B aligned
    {
        const float4* src4 = (const float4*)outsm;
        float4*       dst4 = (float4*)(out + ((size_t)n * CCH + c0) * (OUTS*OUTS));
        #pragma unroll
        for (int i = tid; i < (CHT * OUTS * OUTS) / 4; i += 256)
            dst4[i] = src4[i];
    }
}

// ---------------------------------------------------------------------------
extern "C" void kernel_launch(void* const* d_in, const int* in_sizes, int n_in,
                              void* d_out, int out_size)
{
    const float* feat  = (const float*)d_in[0];
    const float* boxes = (const float*)d_in[1];
    const int*   fidx  = (const int*)d_in[2];
    float*       out   = (float*)d_out;

    const int roi_smem = (CHT * PSTR + CHT * OUTS * OUTS) * (int)sizeof(float); // 23,296 B
    cudaFuncSetAttribute(fused_kernel,
                         cudaFuncAttributeMaxDynamicSharedMemorySize, roi_smem);

    fused_kernel<<<ROI_BLOCKS + SNODE_BLOCKS, 256, roi_smem>>>(feat, boxes, fidx, out);
}

// round 6
// speedup vs baseline: 2.3141x; 1.1045x over previous
#include <cuda_runtime.h>
#include <cstdint>

// Problem constants (fixed shapes)
#define VF    128            // V*F = 8*16
#define CCH   1024
#define HH    14
#define WW    14
#define NBOX  768
#define GG    8              // grid = OUT_SIZE+1
#define OUTS  7
#define CHT   32             // channels per block tile
#define TILES (CCH / CHT)    // 32
#define PSTR  134            // padded plane stride; EVEN (8B cp.async), 134%32=6
#define SCALE (1.0f/16.0f)

#define ROI_BLOCKS   (NBOX * TILES)                      // 24576
#define SNODE_BLOCKS ((VF * CCH) / 8)                    // 16384

#define ROI_COUNT   ((size_t)NBOX * CCH * OUTS * OUTS)   // 38,535,168
#define SNODE_OFF   (ROI_COUNT)
#define FAKE_OFF    (SNODE_OFF + (size_t)VF * CCH)       // 38,666,240

__device__ __forceinline__ void cp_async8(unsigned int smem_dst, const void* gmem_src) {
    asm volatile("cp.async.ca.shared.global [%0], [%1], 8;\n"
                 :: "r"(smem_dst), "l"(gmem_src) : "memory");
}

// ---------------------------------------------------------------------------
// Fused kernel. Blocks [0, ROI_BLOCKS) do RoIAlignAvg; the rest do the
// s_node mean + fake_h_s slice.
// ---------------------------------------------------------------------------
__global__ __launch_bounds__(256, 8) void fused_kernel(
    const float* __restrict__ feat,
    const float* __restrict__ boxes,
    const int*   __restrict__ fidx,
    float*       __restrict__ out)
{
    extern __shared__ float sm[];

    if (blockIdx.x >= ROI_BLOCKS) {
        // ---------------- snode + fake_h_s branch -------------------------
        const int warp = threadIdx.x >> 5;
        const int lane = threadIdx.x & 31;
        const size_t planeidx = (size_t)(blockIdx.x - ROI_BLOCKS) * 8 + warp;

        const float* src  = feat + planeidx * (HH*WW);
        float*       fake = out + FAKE_OFF + planeidx * 144;

        float sum = 0.0f;
        #pragma unroll
        for (int k = 0; k < 7; ++k) {
            const int r = lane + k * 32;
            if (r < HH*WW) {
                const float v = src[r];
                sum += v;
                const int y = r / WW;
                const int x = r - y * WW;
                if (y >= 1 && y <= 12 && x >= 1 && x <= 12)
                    fake[(y-1)*12 + (x-1)] = v;
            }
        }
        #pragma unroll
        for (int o = 16; o; o >>= 1)
            sum += __shfl_down_sync(0xFFFFFFFFu, sum, o);
        if (lane == 0)
            out[SNODE_OFF + planeidx] = sum * (1.0f / 196.0f);
        return;
    }

    // -------------------------- RoI branch --------------------------------
    float* plane = sm;                     // CHT * PSTR floats
    float* outsm = sm + CHT * PSTR;        // CHT * 49 floats

    const int tid  = threadIdx.x;
    const int warp = tid >> 5, lane = tid & 31;
    const int n    = blockIdx.x / TILES;
    const int c0   = (blockIdx.x % TILES) * CHT;

    // ---- geometry in registers (no prolog barrier) ----
    const float bx1 = boxes[n*4+0]*SCALE, by1 = boxes[n*4+1]*SCALE;
    const float bx2 = boxes[n*4+2]*SCALE, by2 = boxes[n*4+3]*SCALE;

    const int ry0   = (int)floorf(fminf(fmaxf(by1, 0.0f), (float)(HH-1)));
    const int ylast = min((int)floorf(fminf(fmaxf(by2, 0.0f), (float)(HH-1))) + 1, HH-1);
    const int L     = (ylast - ry0 + 1) * WW;    // contiguous span, even, <= 126

    const int b = fidx[n];
    const float* fbase = feat + ((size_t)b * CCH + c0) * (HH*WW) + ry0 * WW;

    // ---- load phase: 8B cp.async (both sides 8B aligned), high MLP ----
    {
        const unsigned int smem_base = (unsigned int)__cvta_generic_to_shared(plane);
        const int Lp = L >> 1;                       // float2 count, <= 63
        #pragma unroll
        for (int j = 0; j < CHT / 8; ++j) {          // 4 channels per warp
            const int c = warp + j * 8;
            const float2*      src = (const float2*)(fbase + c * (HH*WW));
            const unsigned int dst = smem_base + (unsigned int)(c * PSTR) * 4u;
            #pragma unroll
            for (int k = 0; k < 2; ++k) {
                const int p = lane + k * 32;
                if (p < Lp) cp_async8(dst + (unsigned int)p * 8u, src + p);
            }
        }
        asm volatile("cp.async.commit_group;\n" ::: "memory");
        asm volatile("cp.async.wait_group 0;\n" ::: "memory");
    }
    __syncthreads();

    // ---- compute phase: thread = (channel, gx). All 256 threads active. ----
    {
        const int gx    = lane & 7;
        const int chsub = lane >> 3;
        const int ch    = warp * 4 + chsub;
        const float* pl = plane + ch * PSTR;

        const float xs0 = fminf(fmaxf(bx1 + (float)gx * (1.0f/7.0f) * (bx2 - bx1),
                                      0.0f), (float)(WW-1));
        const int   xa  = (int)floorf(xs0);
        const int   xb  = min(xa + 1, WW-1);
        const float wx  = xs0 - (float)xa;

        int   curA = -1, curB = -1;
        float a0 = 0.f, a1 = 0.f, b0 = 0.f, b1 = 0.f;
        float xs_prev = 0.f;

        #pragma unroll
        for (int gy = 0; gy < GG; ++gy) {
            const float ys = fminf(fmaxf(by1 + (float)gy * (1.0f/7.0f) * (by2 - by1),
                                         0.0f), (float)(HH-1));
            const int y0i = (int)floorf(ys);
            const int y1i = min(y0i + 1, HH-1);
            const float wy = ys - (float)y0i;
            const int rA = y0i - ry0;
            const int rB = y1i - ry0;
            if (rA != curA) {                 // warp-uniform branch
                if (rA == curB) { a0 = b0; a1 = b1; }
                else            { a0 = pl[rA*WW + xa]; a1 = pl[rA*WW + xb]; }
                curA = rA;
            }
            if (rB != curB) {                 // warp-uniform branch
                b0 = pl[rB*WW + xa]; b1 = pl[rB*WW + xb];
                curB = rB;
            }
            const float top = a0 + wx * (a1 - a0);
            const float bot = b0 + wx * (b1 - b0);
            const float g   = top + wy * (bot - top);
            // x-pool: neighbor gx+1 within the 8-lane group
            const float gr = __shfl_down_sync(0xFFFFFFFFu, g, 1, 8);
            const float xsum = g + gr;
            if (gy > 0 && gx < OUTS)
                outsm[ch * (OUTS*OUTS) + (gy-1) * OUTS + gx] = 0.25f * (xs_prev + xsum);
            xs_prev = xsum;
        }
    }
    __syncthreads();

    // ---- store phase: vectorized contiguous coalesced copy ----
    // c0 multiple of 32 -> output byte offset multiple of 6272 -> 16B aligned
    {
        const float4* src4 = (const float4*)outsm;
        float4*       dst4 = (float4*)(out + ((size_t)n * CCH + c0) * (OUTS*OUTS));
        #pragma unroll
        for (int i = tid; i < (CHT * OUTS * OUTS) / 4; i += 256)
            dst4[i] = src4[i];
    }
}

// ---------------------------------------------------------------------------
extern "C" void kernel_launch(void* const* d_in, const int* in_sizes, int n_in,
                              void* d_out, int out_size)
{
    const float* feat  = (const float*)d_in[0];
    const float* boxes = (const float*)d_in[1];
    const int*   fidx  = (const int*)d_in[2];
    float*       out   = (float*)d_out;

    const int roi_smem = (CHT * PSTR + CHT * OUTS * OUTS) * (int)sizeof(float); // 23,424 B
    cudaFuncSetAttribute(fused_kernel,
                         cudaFuncAttributeMaxDynamicSharedMemorySize, roi_smem);

    fused_kernel<<<ROI_BLOCKS + SNODE_BLOCKS, 256, roi_smem>>>(feat, boxes, fidx, out);
}